// round 1
// baseline (speedup 1.0000x reference)
#include <cuda_runtime.h>
#include <cstddef>

#define DIM 128
#define MAXN 100000

// Scratch: device globals (no allocation allowed in kernel_launch).
__device__ float g_h[(size_t)MAXN * DIM];     // node features between layers
__device__ float g_agg[(size_t)MAXN * DIM];   // scatter-add accumulator
__device__ float g_deg_out[MAXN];             // becomes norm_s in place
__device__ float g_deg_in[MAXN];              // becomes norm_d in place

// ---------------------------------------------------------------------------
// Utility kernels
// ---------------------------------------------------------------------------
__global__ void zero_scalar_kernel(float* __restrict__ p, int n) {
    int i = blockIdx.x * blockDim.x + threadIdx.x;
    if (i < n) p[i] = 0.0f;
}

__global__ void zero_vec4_kernel(float4* __restrict__ p, int n4) {
    int i = blockIdx.x * blockDim.x + threadIdx.x;
    if (i < n4) p[i] = make_float4(0.f, 0.f, 0.f, 0.f);
}

__global__ void deg_kernel(const int* __restrict__ src, const int* __restrict__ dst,
                           float* __restrict__ dout, float* __restrict__ din, int E) {
    int e = blockIdx.x * blockDim.x + threadIdx.x;
    if (e < E) {
        atomicAdd(dout + src[e], 1.0f);
        atomicAdd(din + dst[e], 1.0f);
    }
}

__global__ void norm_kernel(float* __restrict__ dout, float* __restrict__ din, int n) {
    int i = blockIdx.x * blockDim.x + threadIdx.x;
    if (i < n) {
        dout[i] = rsqrtf(fmaxf(dout[i], 1.0f));
        din[i]  = rsqrtf(fmaxf(din[i], 1.0f));
    }
}

// ---------------------------------------------------------------------------
// Edge gather->scale->scatter-add: one warp per edge, float4 per lane.
// agg[dst] += h[src] * norm_s[src]
// ---------------------------------------------------------------------------
__global__ void edge_kernel(const float* __restrict__ h,
                            const int* __restrict__ src,
                            const int* __restrict__ dst,
                            const float* __restrict__ norm_s,
                            float* __restrict__ agg, int E) {
    int g = blockIdx.x * blockDim.x + threadIdx.x;
    int e = g >> 5;
    if (e >= E) return;
    int lane = g & 31;
    int s = __ldg(src + e);
    int d = __ldg(dst + e);
    float ns = __ldg(norm_s + s);
    float4 v = __ldg((const float4*)(h + (size_t)s * DIM) + lane);
    v.x *= ns; v.y *= ns; v.z *= ns; v.w *= ns;
    float* p = agg + (size_t)d * DIM + lane * 4;
    asm volatile("red.global.add.v4.f32 [%0], {%1,%2,%3,%4};"
                 :: "l"(p), "f"(v.x), "f"(v.y), "f"(v.z), "f"(v.w)
                 : "memory");
}

// ---------------------------------------------------------------------------
// GEMM: out[M,128] = f(A[M,128] (optionally * normd[row]) @ W[128,128] + bias)
// If RELU_RES: out = res + relu(z), else out = z.
// Block: 256 threads, BM=64 rows, full N=K=128. Dynamic smem: A tile + W.
// Each thread computes a 4x8 register tile.
// ---------------------------------------------------------------------------
template <bool SCALE_A, bool RELU_RES>
__global__ void gemm_kernel(const float* __restrict__ A,
                            const float* __restrict__ W,
                            const float* __restrict__ bias,
                            const float* __restrict__ normd,
                            const float* __restrict__ res,
                            float* __restrict__ out, int M) {
    extern __shared__ float smem[];
    float* sA = smem;              // [64][132] padded
    float* sW = smem + 64 * 132;   // [128][128]

    const int tid = threadIdx.x;      // 0..255
    const int row0 = blockIdx.x * 64;

    // Load W (128x128 = 4096 float4, 16 per thread)
    {
        const float4* W4 = (const float4*)W;
        float4* sW4 = (float4*)sW;
#pragma unroll
        for (int i = 0; i < 16; i++) sW4[tid + i * 256] = __ldg(W4 + tid + i * 256);
    }

    // Load A tile (64 rows x 32 float4 = 2048 float4, 8 per thread)
#pragma unroll
    for (int i = 0; i < 8; i++) {
        int idx = tid + i * 256;
        int r = idx >> 5;
        int c4 = idx & 31;
        int grow = row0 + r;
        float4 v = make_float4(0.f, 0.f, 0.f, 0.f);
        if (grow < M) {
            v = __ldg((const float4*)(A + (size_t)grow * DIM) + c4);
            if (SCALE_A) {
                float nd = __ldg(normd + grow);
                v.x *= nd; v.y *= nd; v.z *= nd; v.w *= nd;
            }
        }
        *(float4*)(sA + r * 132 + c4 * 4) = v;
    }
    __syncthreads();

    const int ty = tid >> 4;      // 0..15
    const int tx = tid & 15;      // 0..15
    const int rb = ty * 4;        // row base in tile
    const int cb = tx * 8;        // col base

    float acc[4][8];
#pragma unroll
    for (int r = 0; r < 4; r++)
#pragma unroll
        for (int c = 0; c < 8; c++) acc[r][c] = 0.f;

#pragma unroll 8
    for (int k = 0; k < 128; k++) {
        float a0 = sA[(rb + 0) * 132 + k];
        float a1 = sA[(rb + 1) * 132 + k];
        float a2 = sA[(rb + 2) * 132 + k];
        float a3 = sA[(rb + 3) * 132 + k];
        float4 w0 = *(const float4*)(sW + k * 128 + cb);
        float4 w1 = *(const float4*)(sW + k * 128 + cb + 4);
        float w[8] = {w0.x, w0.y, w0.z, w0.w, w1.x, w1.y, w1.z, w1.w};
#pragma unroll
        for (int c = 0; c < 8; c++) {
            acc[0][c] = fmaf(a0, w[c], acc[0][c]);
            acc[1][c] = fmaf(a1, w[c], acc[1][c]);
            acc[2][c] = fmaf(a2, w[c], acc[2][c]);
            acc[3][c] = fmaf(a3, w[c], acc[3][c]);
        }
    }

    // Epilogue
    float bv[8];
#pragma unroll
    for (int c = 0; c < 8; c++) bv[c] = __ldg(bias + cb + c);

#pragma unroll
    for (int r = 0; r < 4; r++) {
        int grow = row0 + rb + r;
        if (grow >= M) break;
        float o[8];
        if (RELU_RES) {
            float4 r0 = __ldg((const float4*)(res + (size_t)grow * DIM + cb));
            float4 r1 = __ldg((const float4*)(res + (size_t)grow * DIM + cb + 4));
            float rr[8] = {r0.x, r0.y, r0.z, r0.w, r1.x, r1.y, r1.z, r1.w};
#pragma unroll
            for (int c = 0; c < 8; c++) {
                float z = acc[r][c] + bv[c];
                z = fmaxf(z, 0.f);
                o[c] = rr[c] + z;
            }
        } else {
#pragma unroll
            for (int c = 0; c < 8; c++) o[c] = acc[r][c] + bv[c];
        }
        float4* op = (float4*)(out + (size_t)grow * DIM + cb);
        op[0] = make_float4(o[0], o[1], o[2], o[3]);
        op[1] = make_float4(o[4], o[5], o[6], o[7]);
    }
}

// ---------------------------------------------------------------------------
// Launch
// ---------------------------------------------------------------------------
extern "C" void kernel_launch(void* const* d_in, const int* in_sizes, int n_in,
                              void* d_out, int out_size) {
    const float* h       = (const float*)d_in[0];
    const int*   src     = (const int*)d_in[1];
    const int*   dst     = (const int*)d_in[2];
    const float* W_embed = (const float*)d_in[3];
    const float* b_embed = (const float*)d_in[4];
    const float* Ws      = (const float*)d_in[5];
    const float* bs      = (const float*)d_in[6];
    float* out = (float*)d_out;

    const int N = in_sizes[0] / DIM;
    const int E = in_sizes[1];

    float *ph, *pagg, *pdo, *pdi;
    cudaGetSymbolAddress((void**)&ph,   g_h);
    cudaGetSymbolAddress((void**)&pagg, g_agg);
    cudaGetSymbolAddress((void**)&pdo,  g_deg_out);
    cudaGetSymbolAddress((void**)&pdi,  g_deg_in);

    const int smem = (64 * 132 + 128 * 128) * (int)sizeof(float);
    cudaFuncSetAttribute((const void*)gemm_kernel<false, false>,
                         cudaFuncAttributeMaxDynamicSharedMemorySize, smem);
    cudaFuncSetAttribute((const void*)gemm_kernel<true, true>,
                         cudaFuncAttributeMaxDynamicSharedMemorySize, smem);

    // 1) degrees -> norms (stored in place in g_deg_out / g_deg_in)
    zero_scalar_kernel<<<(N + 255) / 256, 256>>>(pdo, N);
    zero_scalar_kernel<<<(N + 255) / 256, 256>>>(pdi, N);
    deg_kernel<<<(E + 255) / 256, 256>>>(src, dst, pdo, pdi, E);
    norm_kernel<<<(N + 255) / 256, 256>>>(pdo, pdi, N);

    // 2) embed: g_h = h @ W_embed + b_embed
    int gemm_blocks = (N + 63) / 64;
    gemm_kernel<false, false><<<gemm_blocks, 256, smem>>>(
        h, W_embed, b_embed, nullptr, nullptr, ph, N);

    // 3) layers
    const int agg4 = N * DIM / 4;
    const long edge_threads = (long)E * 32;
    const int edge_blocks = (int)((edge_threads + 255) / 256);
    for (int i = 0; i < 4; i++) {
        zero_vec4_kernel<<<(agg4 + 255) / 256, 256>>>((float4*)pagg, agg4);
        edge_kernel<<<edge_blocks, 256>>>(ph, src, dst, pdo, pagg, E);
        const float* Wi = Ws + (size_t)i * DIM * DIM;
        const float* bi = bs + (size_t)i * DIM;
        float* o = (i == 3) ? out : ph;
        gemm_kernel<true, true><<<gemm_blocks, 256, smem>>>(
            pagg, Wi, bi, pdi, ph, o, N);
    }
}

// round 2
// speedup vs baseline: 1.5432x; 1.5432x over previous
#include <cuda_runtime.h>
#include <cstddef>

#define DIM 128
#define MAXN 100000
#define MAXE 1600000

// Scratch device globals (no allocation allowed in kernel_launch).
__device__ float g_h[(size_t)MAXN * DIM];     // node features between layers
__device__ float g_agg[(size_t)MAXN * DIM];   // aggregation result (GEMM input)
__device__ int   g_cnt_out[MAXN];
__device__ int   g_cnt_in[MAXN];
__device__ float g_norm_s[MAXN];
__device__ float g_norm_d[MAXN];
__device__ int   g_row_ptr[MAXN + 1];
__device__ int   g_cursor[MAXN];
__device__ int   g_csr_src[MAXE];
__device__ float g_csr_norm[MAXE];

// ---------------------------------------------------------------------------
__global__ void zero_int2_kernel(int* __restrict__ a, int* __restrict__ b, int n) {
    int i = blockIdx.x * blockDim.x + threadIdx.x;
    if (i < n) { a[i] = 0; b[i] = 0; }
}

__global__ void count_kernel(const int* __restrict__ src, const int* __restrict__ dst,
                             int* __restrict__ cout, int* __restrict__ cin, int E) {
    int e = blockIdx.x * blockDim.x + threadIdx.x;
    if (e < E) {
        atomicAdd(cout + src[e], 1);
        atomicAdd(cin + dst[e], 1);
    }
}

__global__ void norm_kernel(const int* __restrict__ cout, const int* __restrict__ cin,
                            float* __restrict__ ns, float* __restrict__ nd, int n) {
    int i = blockIdx.x * blockDim.x + threadIdx.x;
    if (i < n) {
        ns[i] = rsqrtf(fmaxf((float)cout[i], 1.0f));
        nd[i] = rsqrtf(fmaxf((float)cin[i], 1.0f));
    }
}

// Single-block exclusive scan of cnt_in -> row_ptr, cursor. 1024 threads.
__global__ void scan_kernel(const int* __restrict__ cnt,
                            int* __restrict__ row_ptr, int* __restrict__ cursor, int n) {
    __shared__ int warp_sums[32];
    __shared__ int carry;
    const int tid = threadIdx.x;
    const int lane = tid & 31;
    const int wid = tid >> 5;
    if (tid == 0) carry = 0;
    __syncthreads();
    for (int base = 0; base < n; base += 1024) {
        int i = base + tid;
        int v = (i < n) ? cnt[i] : 0;
        // inclusive warp scan
        int x = v;
#pragma unroll
        for (int o = 1; o < 32; o <<= 1) {
            int y = __shfl_up_sync(0xffffffffu, x, o);
            if (lane >= o) x += y;
        }
        if (lane == 31) warp_sums[wid] = x;
        __syncthreads();
        if (wid == 0) {
            int s = warp_sums[lane];
#pragma unroll
            for (int o = 1; o < 32; o <<= 1) {
                int y = __shfl_up_sync(0xffffffffu, s, o);
                if (lane >= o) s += y;
            }
            warp_sums[lane] = s;
        }
        __syncthreads();
        int prefix = carry + (wid > 0 ? warp_sums[wid - 1] : 0) + (x - v); // exclusive
        if (i < n) { row_ptr[i] = prefix; cursor[i] = prefix; }
        __syncthreads();
        if (tid == 0) carry += warp_sums[31];
        __syncthreads();
    }
    if (tid == 0) row_ptr[n] = carry;
}

__global__ void scatter_kernel(const int* __restrict__ src, const int* __restrict__ dst,
                               const float* __restrict__ ns,
                               int* __restrict__ cursor,
                               int* __restrict__ csr_src, float* __restrict__ csr_norm,
                               int E) {
    int e = blockIdx.x * blockDim.x + threadIdx.x;
    if (e < E) {
        int s = src[e];
        int d = dst[e];
        int pos = atomicAdd(cursor + d, 1);
        csr_src[pos] = s;
        csr_norm[pos] = __ldg(ns + s);
    }
}

// ---------------------------------------------------------------------------
// Aggregation: one warp per dst node. agg[n] = norm_d[n] * sum_e ns_e * h[src_e]
// ---------------------------------------------------------------------------
__global__ void agg_kernel(const float* __restrict__ h,
                           const int* __restrict__ row_ptr,
                           const int* __restrict__ csr_src,
                           const float* __restrict__ csr_norm,
                           const float* __restrict__ norm_d,
                           float* __restrict__ agg, int N) {
    int g = blockIdx.x * blockDim.x + threadIdx.x;
    int node = g >> 5;
    if (node >= N) return;
    int lane = g & 31;
    int beg = __ldg(row_ptr + node);
    int end = __ldg(row_ptr + node + 1);
    const float4* h4 = (const float4*)h;

    float4 acc = make_float4(0.f, 0.f, 0.f, 0.f);
    int j = beg;
    // 2-way pipelined loop to expose MLP
    for (; j + 1 < end; j += 2) {
        int s0 = __ldg(csr_src + j);
        int s1 = __ldg(csr_src + j + 1);
        float n0 = __ldg(csr_norm + j);
        float n1 = __ldg(csr_norm + j + 1);
        float4 v0 = __ldg(h4 + (size_t)s0 * 32 + lane);
        float4 v1 = __ldg(h4 + (size_t)s1 * 32 + lane);
        acc.x = fmaf(v0.x, n0, acc.x); acc.y = fmaf(v0.y, n0, acc.y);
        acc.z = fmaf(v0.z, n0, acc.z); acc.w = fmaf(v0.w, n0, acc.w);
        acc.x = fmaf(v1.x, n1, acc.x); acc.y = fmaf(v1.y, n1, acc.y);
        acc.z = fmaf(v1.z, n1, acc.z); acc.w = fmaf(v1.w, n1, acc.w);
    }
    if (j < end) {
        int s0 = __ldg(csr_src + j);
        float n0 = __ldg(csr_norm + j);
        float4 v0 = __ldg(h4 + (size_t)s0 * 32 + lane);
        acc.x = fmaf(v0.x, n0, acc.x); acc.y = fmaf(v0.y, n0, acc.y);
        acc.z = fmaf(v0.z, n0, acc.z); acc.w = fmaf(v0.w, n0, acc.w);
    }
    float nd = __ldg(norm_d + node);
    acc.x *= nd; acc.y *= nd; acc.z *= nd; acc.w *= nd;
    ((float4*)agg)[(size_t)node * 32 + lane] = acc;
}

// ---------------------------------------------------------------------------
// GEMM: out[M,128] = f(A[M,128] @ W[128,128] + bias)
// If RELU_RES: out = res + relu(z), else out = z.
// ---------------------------------------------------------------------------
template <bool RELU_RES>
__global__ void gemm_kernel(const float* __restrict__ A,
                            const float* __restrict__ W,
                            const float* __restrict__ bias,
                            const float* __restrict__ res,
                            float* __restrict__ out, int M) {
    extern __shared__ float smem[];
    float* sA = smem;              // [64][132] padded
    float* sW = smem + 64 * 132;   // [128][128]

    const int tid = threadIdx.x;      // 0..255
    const int row0 = blockIdx.x * 64;

    // Load W (128x128 = 4096 float4, 16 per thread)
    {
        const float4* W4 = (const float4*)W;
        float4* sW4 = (float4*)sW;
#pragma unroll
        for (int i = 0; i < 16; i++) sW4[tid + i * 256] = __ldg(W4 + tid + i * 256);
    }

    // Load A tile (64 rows x 32 float4)
#pragma unroll
    for (int i = 0; i < 8; i++) {
        int idx = tid + i * 256;
        int r = idx >> 5;
        int c4 = idx & 31;
        int grow = row0 + r;
        float4 v = make_float4(0.f, 0.f, 0.f, 0.f);
        if (grow < M) v = __ldg((const float4*)(A + (size_t)grow * DIM) + c4);
        *(float4*)(sA + r * 132 + c4 * 4) = v;
    }
    __syncthreads();

    const int ty = tid >> 4;
    const int tx = tid & 15;
    const int rb = ty * 4;
    const int cb = tx * 8;

    float acc[4][8];
#pragma unroll
    for (int r = 0; r < 4; r++)
#pragma unroll
        for (int c = 0; c < 8; c++) acc[r][c] = 0.f;

#pragma unroll 8
    for (int k = 0; k < 128; k++) {
        float a0 = sA[(rb + 0) * 132 + k];
        float a1 = sA[(rb + 1) * 132 + k];
        float a2 = sA[(rb + 2) * 132 + k];
        float a3 = sA[(rb + 3) * 132 + k];
        float4 w0 = *(const float4*)(sW + k * 128 + cb);
        float4 w1 = *(const float4*)(sW + k * 128 + cb + 4);
        float w[8] = {w0.x, w0.y, w0.z, w0.w, w1.x, w1.y, w1.z, w1.w};
#pragma unroll
        for (int c = 0; c < 8; c++) {
            acc[0][c] = fmaf(a0, w[c], acc[0][c]);
            acc[1][c] = fmaf(a1, w[c], acc[1][c]);
            acc[2][c] = fmaf(a2, w[c], acc[2][c]);
            acc[3][c] = fmaf(a3, w[c], acc[3][c]);
        }
    }

    float bv[8];
#pragma unroll
    for (int c = 0; c < 8; c++) bv[c] = __ldg(bias + cb + c);

#pragma unroll
    for (int r = 0; r < 4; r++) {
        int grow = row0 + rb + r;
        if (grow >= M) break;
        float o[8];
        if (RELU_RES) {
            float4 r0 = __ldg((const float4*)(res + (size_t)grow * DIM + cb));
            float4 r1 = __ldg((const float4*)(res + (size_t)grow * DIM + cb + 4));
            float rr[8] = {r0.x, r0.y, r0.z, r0.w, r1.x, r1.y, r1.z, r1.w};
#pragma unroll
            for (int c = 0; c < 8; c++) {
                float z = acc[r][c] + bv[c];
                z = fmaxf(z, 0.f);
                o[c] = rr[c] + z;
            }
        } else {
#pragma unroll
            for (int c = 0; c < 8; c++) o[c] = acc[r][c] + bv[c];
        }
        float4* op = (float4*)(out + (size_t)grow * DIM + cb);
        op[0] = make_float4(o[0], o[1], o[2], o[3]);
        op[1] = make_float4(o[4], o[5], o[6], o[7]);
    }
}

// ---------------------------------------------------------------------------
extern "C" void kernel_launch(void* const* d_in, const int* in_sizes, int n_in,
                              void* d_out, int out_size) {
    const float* h       = (const float*)d_in[0];
    const int*   src     = (const int*)d_in[1];
    const int*   dst     = (const int*)d_in[2];
    const float* W_embed = (const float*)d_in[3];
    const float* b_embed = (const float*)d_in[4];
    const float* Ws      = (const float*)d_in[5];
    const float* bs      = (const float*)d_in[6];
    float* out = (float*)d_out;

    const int N = in_sizes[0] / DIM;
    const int E = in_sizes[1];

    float *ph, *pagg, *pns, *pnd, *pcsrn;
    int *pco, *pci, *prow, *pcur, *pcsrs;
    cudaGetSymbolAddress((void**)&ph,    g_h);
    cudaGetSymbolAddress((void**)&pagg,  g_agg);
    cudaGetSymbolAddress((void**)&pco,   g_cnt_out);
    cudaGetSymbolAddress((void**)&pci,   g_cnt_in);
    cudaGetSymbolAddress((void**)&pns,   g_norm_s);
    cudaGetSymbolAddress((void**)&pnd,   g_norm_d);
    cudaGetSymbolAddress((void**)&prow,  g_row_ptr);
    cudaGetSymbolAddress((void**)&pcur,  g_cursor);
    cudaGetSymbolAddress((void**)&pcsrs, g_csr_src);
    cudaGetSymbolAddress((void**)&pcsrn, g_csr_norm);

    const int smem = (64 * 132 + 128 * 128) * (int)sizeof(float);
    cudaFuncSetAttribute((const void*)gemm_kernel<false>,
                         cudaFuncAttributeMaxDynamicSharedMemorySize, smem);
    cudaFuncSetAttribute((const void*)gemm_kernel<true>,
                         cudaFuncAttributeMaxDynamicSharedMemorySize, smem);

    // 1) CSR build: degrees -> norms -> row_ptr -> scatter (src, norm_s)
    zero_int2_kernel<<<(N + 255) / 256, 256>>>(pco, pci, N);
    count_kernel<<<(E + 255) / 256, 256>>>(src, dst, pco, pci, E);
    norm_kernel<<<(N + 255) / 256, 256>>>(pco, pci, pns, pnd, N);
    scan_kernel<<<1, 1024>>>(pci, prow, pcur, N);
    scatter_kernel<<<(E + 255) / 256, 256>>>(src, dst, pns, pcur, pcsrs, pcsrn, E);

    // 2) embed: g_h = h @ W_embed + b_embed
    const int gemm_blocks = (N + 63) / 64;
    gemm_kernel<false><<<gemm_blocks, 256, smem>>>(h, W_embed, b_embed, nullptr, ph, N);

    // 3) layers
    const int agg_blocks = (N * 32 + 255) / 256;
    for (int i = 0; i < 4; i++) {
        agg_kernel<<<agg_blocks, 256>>>(ph, prow, pcsrs, pcsrn, pnd, pagg, N);
        const float* Wi = Ws + (size_t)i * DIM * DIM;
        const float* bi = bs + (size_t)i * DIM;
        float* o = (i == 3) ? out : ph;
        gemm_kernel<true><<<gemm_blocks, 256, smem>>>(pagg, Wi, bi, ph, o, N);
    }
}

// round 4
// speedup vs baseline: 2.7533x; 1.7842x over previous
#include <cuda_runtime.h>
#include <cuda_bf16.h>
#include <cstdint>
#include <cstddef>

#define DIM 128
#define MAXN 100000
#define MAXE 1600000

// ---------------------------------------------------------------------------
// Scratch device globals
// ---------------------------------------------------------------------------
__device__ float    g_h[(size_t)MAXN * DIM];
__device__ float    g_agg[(size_t)MAXN * DIM];
__device__ int      g_cnt_out[MAXN];
__device__ int      g_cnt_in[MAXN];
__device__ float    g_norm_s[MAXN];
__device__ float    g_norm_d[MAXN];
__device__ int      g_row_beg[MAXN];
__device__ int      g_cursor[MAXN];
__device__ int      g_csr_src[MAXE];
__device__ float    g_csr_norm[MAXE];
__device__ int      g_total;
// W^T images: [n][k] bf16, hi and lo parts, for 5 weight matrices.
__device__ uint16_t g_wh[5 * DIM * DIM];
__device__ uint16_t g_wl[5 * DIM * DIM];

// ---------------------------------------------------------------------------
// CSR build kernels
// ---------------------------------------------------------------------------
__global__ void zero_kernel(int* __restrict__ a, int* __restrict__ b,
                            int* __restrict__ total, int n) {
    int i = blockIdx.x * blockDim.x + threadIdx.x;
    if (i < n) { a[i] = 0; b[i] = 0; }
    if (i == 0) *total = 0;
}

__global__ void count_kernel(const int* __restrict__ src, const int* __restrict__ dst,
                             int* __restrict__ cout, int* __restrict__ cin, int E) {
    int e = blockIdx.x * blockDim.x + threadIdx.x;
    if (e < E) {
        atomicAdd(cout + src[e], 1);
        atomicAdd(cin + dst[e], 1);
    }
}

__global__ void norm_kernel(const int* __restrict__ cout, const int* __restrict__ cin,
                            float* __restrict__ ns, float* __restrict__ nd, int n) {
    int i = blockIdx.x * blockDim.x + threadIdx.x;
    if (i < n) {
        ns[i] = rsqrtf(fmaxf((float)cout[i], 1.0f));
        nd[i] = rsqrtf(fmaxf((float)cin[i], 1.0f));
    }
}

// Row offsets via warp-aggregated atomic allocation (placement nondeterministic,
// per-node edge sets unchanged -> same sums).
__global__ void rowbeg_kernel(const int* __restrict__ cnt, int* __restrict__ beg,
                              int* __restrict__ cursor, int* __restrict__ total, int n) {
    int i = blockIdx.x * blockDim.x + threadIdx.x;
    int lane = threadIdx.x & 31;
    int v = (i < n) ? cnt[i] : 0;
    int x = v;
#pragma unroll
    for (int o = 1; o < 32; o <<= 1) {
        int y = __shfl_up_sync(0xffffffffu, x, o);
        if (lane >= o) x += y;
    }
    int wsum = __shfl_sync(0xffffffffu, x, 31);
    int base = 0;
    if (lane == 31) base = atomicAdd(total, wsum);
    base = __shfl_sync(0xffffffffu, base, 31);
    if (i < n) {
        int b = base + x - v;
        beg[i] = b;
        cursor[i] = b;
    }
}

__global__ void scatter_kernel(const int* __restrict__ src, const int* __restrict__ dst,
                               const float* __restrict__ ns, int* __restrict__ cursor,
                               int* __restrict__ csr_src, float* __restrict__ csr_norm,
                               int E) {
    int e = blockIdx.x * blockDim.x + threadIdx.x;
    if (e < E) {
        int s = src[e];
        int d = dst[e];
        int pos = atomicAdd(cursor + d, 1);
        csr_src[pos] = s;
        csr_norm[pos] = __ldg(ns + s);
    }
}

// ---------------------------------------------------------------------------
// Aggregation: one warp per dst node.
// ---------------------------------------------------------------------------
__global__ void agg_kernel(const float* __restrict__ h,
                           const int* __restrict__ row_beg,
                           const int* __restrict__ cnt_in,
                           const int* __restrict__ csr_src,
                           const float* __restrict__ csr_norm,
                           const float* __restrict__ norm_d,
                           float* __restrict__ agg, int N) {
    int g = blockIdx.x * blockDim.x + threadIdx.x;
    int node = g >> 5;
    if (node >= N) return;
    int lane = g & 31;
    int beg = __ldg(row_beg + node);
    int end = beg + __ldg(cnt_in + node);
    const float4* h4 = (const float4*)h;

    float4 acc = make_float4(0.f, 0.f, 0.f, 0.f);
    int j = beg;
    for (; j + 1 < end; j += 2) {
        int s0 = __ldg(csr_src + j);
        int s1 = __ldg(csr_src + j + 1);
        float n0 = __ldg(csr_norm + j);
        float n1 = __ldg(csr_norm + j + 1);
        float4 v0 = __ldg(h4 + (size_t)s0 * 32 + lane);
        float4 v1 = __ldg(h4 + (size_t)s1 * 32 + lane);
        acc.x = fmaf(v0.x, n0, acc.x); acc.y = fmaf(v0.y, n0, acc.y);
        acc.z = fmaf(v0.z, n0, acc.z); acc.w = fmaf(v0.w, n0, acc.w);
        acc.x = fmaf(v1.x, n1, acc.x); acc.y = fmaf(v1.y, n1, acc.y);
        acc.z = fmaf(v1.z, n1, acc.z); acc.w = fmaf(v1.w, n1, acc.w);
    }
    if (j < end) {
        int s0 = __ldg(csr_src + j);
        float n0 = __ldg(csr_norm + j);
        float4 v0 = __ldg(h4 + (size_t)s0 * 32 + lane);
        acc.x = fmaf(v0.x, n0, acc.x); acc.y = fmaf(v0.y, n0, acc.y);
        acc.z = fmaf(v0.z, n0, acc.z); acc.w = fmaf(v0.w, n0, acc.w);
    }
    float nd = __ldg(norm_d + node);
    acc.x *= nd; acc.y *= nd; acc.z *= nd; acc.w *= nd;
    ((float4*)agg)[(size_t)node * 32 + lane] = acc;
}

// ---------------------------------------------------------------------------
// W image prep: Wt[n][k] = W[k][n], bf16 hi/lo split.
// ---------------------------------------------------------------------------
__global__ void wprep_kernel(const float* __restrict__ W,
                             uint16_t* __restrict__ wh, uint16_t* __restrict__ wl) {
    int t = blockIdx.x * blockDim.x + threadIdx.x;
    if (t >= DIM * DIM) return;
    int k = t >> 7;
    int n = t & 127;
    float w = W[t];
    __nv_bfloat16 hb = __float2bfloat16_rn(w);
    float lo = w - __bfloat162float(hb);
    __nv_bfloat16 lb = __float2bfloat16_rn(lo);
    wh[n * DIM + k] = reinterpret_cast<uint16_t&>(hb);
    wl[n * DIM + k] = reinterpret_cast<uint16_t&>(lb);
}

// ---------------------------------------------------------------------------
// bf16x3 mma.sync GEMM: out[M,128] = f(A[M,128] @ W[128,128] + bias)
// 256 threads = 8 warps (4x2). Warp tile 32x64. Persistent CTAs.
// SMEM: bias 512B | A_hi 32K | A_lo 32K | W_hi 32K | W_lo 32K (XOR swizzled)
// ---------------------------------------------------------------------------
#define SM_AH 1024
#define SM_AL (1024 + 32768)
#define SM_WH (1024 + 65536)
#define SM_WL (1024 + 98304)
#define SM_BYTES (1024 + 131072)

__device__ __forceinline__ uint32_t smem_u32(const void* p) {
    uint32_t a;
    asm("{ .reg .u64 t; cvta.to.shared.u64 t, %1; cvt.u32.u64 %0, t; }"
        : "=r"(a) : "l"(p));
    return a;
}
__device__ __forceinline__ void ldsm4(uint32_t* r, uint32_t addr) {
    asm volatile("ldmatrix.sync.aligned.m8n8.x4.shared.b16 {%0,%1,%2,%3}, [%4];"
                 : "=r"(r[0]), "=r"(r[1]), "=r"(r[2]), "=r"(r[3]) : "r"(addr));
}
__device__ __forceinline__ void mma16816(float* c, const uint32_t* a,
                                         uint32_t b0, uint32_t b1) {
    asm volatile("mma.sync.aligned.m16n8k16.row.col.f32.bf16.bf16.f32 "
                 "{%0,%1,%2,%3}, {%4,%5,%6,%7}, {%8,%9}, {%0,%1,%2,%3};"
                 : "+f"(c[0]), "+f"(c[1]), "+f"(c[2]), "+f"(c[3])
                 : "r"(a[0]), "r"(a[1]), "r"(a[2]), "r"(a[3]), "r"(b0), "r"(b1));
}

template <bool RELU_RES>
__global__ void __launch_bounds__(256, 1)
mma_gemm(const float* __restrict__ A,
         const uint16_t* __restrict__ wh, const uint16_t* __restrict__ wl,
         const float* __restrict__ bias, const float* __restrict__ res,
         float* __restrict__ out, int M, int ntiles) {
    extern __shared__ char smem[];
    const uint32_t sb = smem_u32(smem);
    const int tid = threadIdx.x;
    const int lane = tid & 31;
    const int wid = tid >> 5;
    const int wm = wid >> 1;   // 0..3
    const int wn = wid & 1;    // 0..1

    // bias -> smem
    if (tid < 128) ((float*)smem)[tid] = __ldg(bias + tid);
    // W hi/lo -> smem (swizzled: 16B chunk at (n, kc): off = n*256 + (kc*16 ^ ((n&7)<<4)))
#pragma unroll
    for (int j = 0; j < 8; j++) {
        int cidx = tid + j * 256;       // 2048 chunks of 16B per image
        int n = cidx >> 4;
        int kc = cidx & 15;
        uint32_t off = (uint32_t)(n * 256 + ((kc * 16) ^ ((n & 7) << 4)));
        *(uint4*)(smem + SM_WH + off) = __ldg((const uint4*)wh + cidx);
        *(uint4*)(smem + SM_WL + off) = __ldg((const uint4*)wl + cidx);
    }
    __syncthreads();

    // bias fragment regs (col = wn*64 + ni*8 + 2*(lane&3))
    float2 bias_r[8];
    {
        const float* sbf = (const float*)smem;
        int colb = wn * 64 + 2 * (lane & 3);
#pragma unroll
        for (int ni = 0; ni < 8; ni++)
            bias_r[ni] = *(const float2*)(sbf + colb + ni * 8);
    }

    // ldmatrix base addresses
    uint32_t aoff[2], axor[2];
#pragma unroll
    for (int mi = 0; mi < 2; mi++) {
        int r = wm * 32 + mi * 16 + (lane & 15);
        aoff[mi] = (uint32_t)(r * 256);
        axor[mi] = (uint32_t)((r & 7) << 4);
    }
    const uint32_t akc = (uint32_t)((lane >> 4) * 16);
    uint32_t boff[4], bxor[4];
#pragma unroll
    for (int pi = 0; pi < 4; pi++) {
        int nB = wn * 64 + pi * 16 + ((lane >> 4) & 1) * 8 + (lane & 7);
        boff[pi] = (uint32_t)(nB * 256);
        bxor[pi] = (uint32_t)((nB & 7) << 4);
    }
    const uint32_t bkc = (uint32_t)(((lane >> 3) & 1) * 16);

    for (int tile = blockIdx.x; tile < ntiles; tile += gridDim.x) {
        const int row0 = tile * 128;

        // ---- A load (fp32) -> bf16 hi/lo -> swizzled smem ----
#pragma unroll
        for (int i = 0; i < 16; i++) {
            int idx = tid + i * 256;
            int r = idx >> 5;
            int c4 = idx & 31;
            int grow = row0 + r;
            float4 v = make_float4(0.f, 0.f, 0.f, 0.f);
            if (grow < M) v = __ldg((const float4*)A + (size_t)grow * 32 + c4);
            __nv_bfloat162 h0 = __float22bfloat162_rn(make_float2(v.x, v.y));
            __nv_bfloat162 h1 = __float22bfloat162_rn(make_float2(v.z, v.w));
            float2 f0 = __bfloat1622float2(h0);
            float2 f1 = __bfloat1622float2(h1);
            __nv_bfloat162 l0 = __float22bfloat162_rn(make_float2(v.x - f0.x, v.y - f0.y));
            __nv_bfloat162 l1 = __float22bfloat162_rn(make_float2(v.z - f1.x, v.w - f1.y));
            uint32_t off = (uint32_t)(r * 256 + ((c4 * 8) ^ ((r & 7) << 4)));
            *(uint2*)(smem + SM_AH + off) =
                make_uint2(reinterpret_cast<uint32_t&>(h0), reinterpret_cast<uint32_t&>(h1));
            *(uint2*)(smem + SM_AL + off) =
                make_uint2(reinterpret_cast<uint32_t&>(l0), reinterpret_cast<uint32_t&>(l1));
        }
        __syncthreads();

        // ---- K loop: 3-pass bf16 split ----
        float acc[2][8][4];
#pragma unroll
        for (int mi = 0; mi < 2; mi++)
#pragma unroll
            for (int ni = 0; ni < 8; ni++)
#pragma unroll
                for (int q = 0; q < 4; q++) acc[mi][ni][q] = 0.f;

#pragma unroll
        for (int ks = 0; ks < 8; ks++) {
            const uint32_t kb = (uint32_t)(ks * 32);
            uint32_t ah[2][4], al[2][4];
#pragma unroll
            for (int mi = 0; mi < 2; mi++) {
                uint32_t co = (kb + akc) ^ axor[mi];
                ldsm4(ah[mi], sb + SM_AH + aoff[mi] + co);
                ldsm4(al[mi], sb + SM_AL + aoff[mi] + co);
            }
            uint32_t bh[4][4], bl[4][4];
#pragma unroll
            for (int pi = 0; pi < 4; pi++) {
                uint32_t co = (kb + bkc) ^ bxor[pi];
                ldsm4(bh[pi], sb + SM_WH + boff[pi] + co);
                ldsm4(bl[pi], sb + SM_WL + boff[pi] + co);
            }
#pragma unroll
            for (int mi = 0; mi < 2; mi++)
#pragma unroll
                for (int pi = 0; pi < 4; pi++) {
                    mma16816(acc[mi][2 * pi + 0], ah[mi], bh[pi][0], bh[pi][1]);
                    mma16816(acc[mi][2 * pi + 1], ah[mi], bh[pi][2], bh[pi][3]);
                    mma16816(acc[mi][2 * pi + 0], ah[mi], bl[pi][0], bl[pi][1]);
                    mma16816(acc[mi][2 * pi + 1], ah[mi], bl[pi][2], bl[pi][3]);
                    mma16816(acc[mi][2 * pi + 0], al[mi], bh[pi][0], bh[pi][1]);
                    mma16816(acc[mi][2 * pi + 1], al[mi], bh[pi][2], bh[pi][3]);
                }
        }

        // ---- Epilogue: bias + relu + residual ----
        const int colb = wn * 64 + 2 * (lane & 3);
#pragma unroll
        for (int mi = 0; mi < 2; mi++) {
            int rbase = row0 + wm * 32 + mi * 16 + (lane >> 2);
#pragma unroll
            for (int hh = 0; hh < 2; hh++) {
                int grow = rbase + hh * 8;
                if (grow < M) {
#pragma unroll
                    for (int ni = 0; ni < 8; ni++) {
                        float z0 = acc[mi][ni][hh * 2 + 0] + bias_r[ni].x;
                        float z1 = acc[mi][ni][hh * 2 + 1] + bias_r[ni].y;
                        int col = colb + ni * 8;
                        if (RELU_RES) {
                            float2 rv = __ldg((const float2*)(res + (size_t)grow * 128 + col));
                            z0 = rv.x + fmaxf(z0, 0.f);
                            z1 = rv.y + fmaxf(z1, 0.f);
                        }
                        *(float2*)(out + (size_t)grow * 128 + col) = make_float2(z0, z1);
                    }
                }
            }
        }
        __syncthreads();
    }
}

// ---------------------------------------------------------------------------
extern "C" void kernel_launch(void* const* d_in, const int* in_sizes, int n_in,
                              void* d_out, int out_size) {
    const float* h       = (const float*)d_in[0];
    const int*   src     = (const int*)d_in[1];
    const int*   dst     = (const int*)d_in[2];
    const float* W_embed = (const float*)d_in[3];
    const float* b_embed = (const float*)d_in[4];
    const float* Ws      = (const float*)d_in[5];
    const float* bs      = (const float*)d_in[6];
    float* out = (float*)d_out;

    const int N = in_sizes[0] / DIM;
    const int E = in_sizes[1];
    const int ntiles = (N + 127) / 128;

    float *ph, *pagg, *pns, *pnd, *pcsrn;
    int *pco, *pci, *pbeg, *pcur, *pcsrs, *ptot;
    uint16_t *pwh, *pwl;
    cudaGetSymbolAddress((void**)&ph,    g_h);
    cudaGetSymbolAddress((void**)&pagg,  g_agg);
    cudaGetSymbolAddress((void**)&pco,   g_cnt_out);
    cudaGetSymbolAddress((void**)&pci,   g_cnt_in);
    cudaGetSymbolAddress((void**)&pns,   g_norm_s);
    cudaGetSymbolAddress((void**)&pnd,   g_norm_d);
    cudaGetSymbolAddress((void**)&pbeg,  g_row_beg);
    cudaGetSymbolAddress((void**)&pcur,  g_cursor);
    cudaGetSymbolAddress((void**)&pcsrs, g_csr_src);
    cudaGetSymbolAddress((void**)&pcsrn, g_csr_norm);
    cudaGetSymbolAddress((void**)&ptot,  g_total);
    cudaGetSymbolAddress((void**)&pwh,   g_wh);
    cudaGetSymbolAddress((void**)&pwl,   g_wl);

    cudaFuncSetAttribute((const void*)mma_gemm<false>,
                         cudaFuncAttributeMaxDynamicSharedMemorySize, SM_BYTES);
    cudaFuncSetAttribute((const void*)mma_gemm<true>,
                         cudaFuncAttributeMaxDynamicSharedMemorySize, SM_BYTES);

    // 1) CSR build
    zero_kernel<<<(N + 255) / 256, 256>>>(pco, pci, ptot, N);
    count_kernel<<<(E + 255) / 256, 256>>>(src, dst, pco, pci, E);
    norm_kernel<<<(N + 255) / 256, 256>>>(pco, pci, pns, pnd, N);
    rowbeg_kernel<<<(N + 255) / 256, 256>>>(pci, pbeg, pcur, ptot, N);
    scatter_kernel<<<(E + 255) / 256, 256>>>(src, dst, pns, pcur, pcsrs, pcsrn, E);

    // 2) W images (bf16 hi/lo, transposed)
    wprep_kernel<<<64, 256>>>(W_embed, pwh, pwl);
    for (int i = 0; i < 4; i++)
        wprep_kernel<<<64, 256>>>(Ws + (size_t)i * DIM * DIM,
                                  pwh + (size_t)(1 + i) * DIM * DIM,
                                  pwl + (size_t)(1 + i) * DIM * DIM);

    // 3) embed GEMM
    const int GG = 152;
    mma_gemm<false><<<GG, 256, SM_BYTES>>>(h, pwh, pwl, b_embed, nullptr, ph, N, ntiles);

    // 4) layers
    const int agg_blocks = (N * 32 + 255) / 256;
    for (int i = 0; i < 4; i++) {
        agg_kernel<<<agg_blocks, 256>>>(ph, pbeg, pci, pcsrs, pcsrn, pnd, pagg, N);
        const float* bi = bs + (size_t)i * DIM;
        float* o = (i == 3) ? out : ph;
        mma_gemm<true><<<GG, 256, SM_BYTES>>>(
            pagg, pwh + (size_t)(1 + i) * DIM * DIM, pwl + (size_t)(1 + i) * DIM * DIM,
            bi, ph, o, N, ntiles);
    }
}